// round 9
// baseline (speedup 1.0000x reference)
#include <cuda_runtime.h>
#include <cuda_fp16.h>
#include <cstdint>

#define BB 16
#define SS 2048
#define DD 128
#define UU 128

// ---------------------------------------------------------------------------
// Scratch (static __device__ — allocation-guard safe)
// ---------------------------------------------------------------------------
__device__ __half g_qh[(size_t)BB * SS * UU];   // q' = (x Wq)*log2e/sqrt(U), fp16 [row][u]
__device__ __half g_kh[(size_t)BB * SS * UU];   // k  =  x Wk, fp16 [row][u]
__device__ __half g_WT[256 * DD];               // [Wq*c | Wk] transposed: [n][d]
__device__ __half g_E[(size_t)BB * SS * SS];    // E[b][i][j] fp16, 128MB
__device__ float g_l[BB * SS];
__device__ float g_w[BB * SS];

// ---------------------------------------------------------------------------
// helpers
// ---------------------------------------------------------------------------
__device__ __forceinline__ uint32_t smem_u32(const void* p) {
    uint32_t a;
    asm("{ .reg .u64 t; cvta.to.shared.u64 t, %1; cvt.u32.u64 %0, t; }" : "=r"(a) : "l"(p));
    return a;
}
__device__ __forceinline__ float ex2f(float x) {
    float r; asm("ex2.approx.f32 %0, %1;" : "=f"(r) : "f"(x)); return r;
}
__device__ __forceinline__ void ldmx4(uint32_t* r, uint32_t addr) {
    asm volatile("ldmatrix.sync.aligned.m8n8.x4.shared.b16 {%0,%1,%2,%3}, [%4];"
                 : "=r"(r[0]), "=r"(r[1]), "=r"(r[2]), "=r"(r[3]) : "r"(addr));
}
__device__ __forceinline__ void mma16816(float* c, const uint32_t* a, uint32_t b0, uint32_t b1) {
    asm volatile(
        "mma.sync.aligned.m16n8k16.row.col.f32.f16.f16.f32 "
        "{%0,%1,%2,%3}, {%4,%5,%6,%7}, {%8,%9}, {%0,%1,%2,%3};"
        : "+f"(c[0]), "+f"(c[1]), "+f"(c[2]), "+f"(c[3])
        : "r"(a[0]), "r"(a[1]), "r"(a[2]), "r"(a[3]), "r"(b0), "r"(b1));
}
__device__ __forceinline__ uint32_t pack_f16x2(float lo, float hi) {
    uint32_t r;
    asm("cvt.rn.f16x2.f32 %0, %1, %2;" : "=r"(r) : "f"(hi), "f"(lo));
    return r;
}

// Swizzled smem tile: rows x 16 uint4 chunks (256B/row), chunk ^= (row&7).
__device__ __forceinline__ int tidx(int row, int chunk) {
    return row * 16 + (chunk ^ (row & 7));
}
__device__ __forceinline__ uint32_t taddr(uint32_t base, int row, int chunk) {
    return base + (uint32_t)tidx(row, chunk) * 16u;
}

// ---------------------------------------------------------------------------
// prep: zero g_l/g_w/out; g_WT[n][d] = (n<128 ? Wq[d][n]*C : Wk[d][n-128]) fp16
// ---------------------------------------------------------------------------
__global__ void prep_kernel(const float* __restrict__ Wq, const float* __restrict__ Wk,
                            float* __restrict__ out) {
    const float C_FOLD = 0.12751744695704165f;  // log2(e)/sqrt(128)
    int idx = blockIdx.x * 256 + threadIdx.x;   // 0..32767
    g_l[idx] = 0.f;
    g_w[idx] = 0.f;
    if (idx < BB * DD) out[idx] = 0.f;
    int n = idx >> 7, d = idx & 127;
    float v = (n < 128) ? Wq[d * 128 + n] * C_FOLD : Wk[d * 128 + (n - 128)];
    g_WT[idx] = __float2half(v);
}

// ---------------------------------------------------------------------------
// GEMM core: 128x128 fp16 mma.sync, K=128 resident, 4 warps, 64x64 warp tile.
// ---------------------------------------------------------------------------
struct Frag { float c[4][8][4]; };

__device__ __forceinline__ void gemm_core(uint32_t aBase, uint32_t bBase, Frag& F) {
    const int lane = threadIdx.x & 31, wid = threadIdx.x >> 5;
    const int wm = (wid & 1) * 64, wn = (wid >> 1) * 64;

    #pragma unroll
    for (int mt = 0; mt < 4; mt++)
        #pragma unroll
        for (int nt = 0; nt < 8; nt++)
            #pragma unroll
            for (int e = 0; e < 4; e++) F.c[mt][nt][e] = 0.f;

    const int l7 = lane & 7, lhi = lane >> 3;

    #pragma unroll
    for (int ks = 0; ks < 8; ks++) {
        uint32_t a[4][4];
        #pragma unroll
        for (int mt = 0; mt < 4; mt++) {
            int row = wm + mt * 16 + l7 + (lhi & 1) * 8;
            int chunk = 2 * ks + (lhi >> 1);
            ldmx4(a[mt], taddr(aBase, row, chunk));
        }
        uint32_t bfr[4][4];
        #pragma unroll
        for (int np = 0; np < 4; np++) {
            int row = wn + np * 16 + l7 + (lhi >> 1) * 8;
            int chunk = 2 * ks + (lhi & 1);
            ldmx4(bfr[np], taddr(bBase, row, chunk));
        }
        #pragma unroll
        for (int mt = 0; mt < 4; mt++)
            #pragma unroll
            for (int np = 0; np < 4; np++) {
                mma16816(F.c[mt][2 * np + 0], a[mt], bfr[np][0], bfr[np][1]);
                mma16816(F.c[mt][2 * np + 1], a[mt], bfr[np][2], bfr[np][3]);
            }
    }
}

__device__ __forceinline__ void stage_sts(char* sm, int row, int col, uint32_t v) {
    uint32_t byte = (uint32_t)tidx(row, col >> 3) * 16u + (uint32_t)(col & 7) * 2u;
    *reinterpret_cast<uint32_t*>(sm + byte) = v;
}

// ---------------------------------------------------------------------------
// proj: rows r0..r0+127 of x (fp32->fp16) @ g_WT half -> q' or k (fp16)
// grid (256, 2), block 128, smem 64KB
// ---------------------------------------------------------------------------
__global__ void __launch_bounds__(128) proj_kernel(const float* __restrict__ x) {
    extern __shared__ char sm[];
    char* As = sm;
    char* Bs = sm + 32768;
    uint32_t aBase = smem_u32(As), bBase = smem_u32(Bs);

    const int tid = threadIdx.x;
    const int r0 = blockIdx.x * 128;
    const int nsel = blockIdx.y;

    {
        const float4* xs = reinterpret_cast<const float4*>(x + (size_t)r0 * DD);
        #pragma unroll
        for (int it = 0; it < 16; it++) {
            int idx = tid + 128 * it;
            int row = idx >> 4, chunk = idx & 15;
            float4 f0 = xs[row * 32 + chunk * 2];
            float4 f1 = xs[row * 32 + chunk * 2 + 1];
            uint4 o;
            o.x = pack_f16x2(f0.x, f0.y);
            o.y = pack_f16x2(f0.z, f0.w);
            o.z = pack_f16x2(f1.x, f1.y);
            o.w = pack_f16x2(f1.z, f1.w);
            reinterpret_cast<uint4*>(As)[tidx(row, chunk)] = o;
        }
        const uint4* ws = reinterpret_cast<const uint4*>(g_WT) + nsel * 128 * 16;
        #pragma unroll
        for (int it = 0; it < 16; it++) {
            int idx = tid + 128 * it;
            int row = idx >> 4, chunk = idx & 15;
            reinterpret_cast<uint4*>(Bs)[tidx(row, chunk)] = ws[idx];
        }
    }
    __syncthreads();

    Frag F;
    gemm_core(aBase, bBase, F);
    __syncthreads();

    const int lane = tid & 31, wid = tid >> 5;
    const int wm = (wid & 1) * 64, wn = (wid >> 1) * 64;
    const int lr = lane >> 2, lc = (lane & 3) * 2;
    #pragma unroll
    for (int mt = 0; mt < 4; mt++)
        #pragma unroll
        for (int nt = 0; nt < 8; nt++) {
            int row = wm + mt * 16 + lr;
            int col = wn + nt * 8 + lc;
            float* cc = F.c[mt][nt];
            stage_sts(As, row,     col, pack_f16x2(cc[0], cc[1]));
            stage_sts(As, row + 8, col, pack_f16x2(cc[2], cc[3]));
        }
    __syncthreads();

    uint4* dst = reinterpret_cast<uint4*>(nsel ? g_kh : g_qh) + (size_t)r0 * 16;
    #pragma unroll
    for (int it = 0; it < 16; it++) {
        int idx = tid + 128 * it;
        int row = idx >> 4, chunk = idx & 15;
        dst[idx] = reinterpret_cast<uint4*>(As)[tidx(row, chunk)];
    }
}

// ---------------------------------------------------------------------------
// s1e: one GEMM pass. E_tile = exp2(q'.k^T); row-sums -> g_l (atomic);
// E stored fp16 to g_E (coalesced). grid (16,16,16), block 128.
// ---------------------------------------------------------------------------
__global__ void __launch_bounds__(128) s1e_kernel() {
    extern __shared__ char sm[];
    char* As = sm;
    char* Bs = sm + 32768;
    uint32_t aBase = smem_u32(As), bBase = smem_u32(Bs);

    const int tid = threadIdx.x;
    const int b = blockIdx.z, i0 = blockIdx.y * 128, j0 = blockIdx.x * 128;

    {
        const uint4* qs = reinterpret_cast<const uint4*>(g_qh) + (size_t)(b * SS + i0) * 16;
        const uint4* ks = reinterpret_cast<const uint4*>(g_kh) + (size_t)(b * SS + j0) * 16;
        #pragma unroll
        for (int it = 0; it < 16; it++) {
            int idx = tid + 128 * it;
            int row = idx >> 4, chunk = idx & 15;
            reinterpret_cast<uint4*>(As)[tidx(row, chunk)] = qs[idx];
            reinterpret_cast<uint4*>(Bs)[tidx(row, chunk)] = ks[idx];
        }
    }
    __syncthreads();

    Frag F;
    gemm_core(aBase, bBase, F);
    __syncthreads();   // all warps done reading tiles; As reusable as staging

    const int lane = tid & 31, wid = tid >> 5;
    const int wm = (wid & 1) * 64, wn = (wid >> 1) * 64;
    const int lr = lane >> 2, lc = (lane & 3) * 2;

    // exp2, stage fp16, accumulate row sums
    #pragma unroll
    for (int mt = 0; mt < 4; mt++) {
        float rlo = 0.f, rhi = 0.f;
        #pragma unroll
        for (int nt = 0; nt < 8; nt++) {
            int row = wm + mt * 16 + lr;
            int col = wn + nt * 8 + lc;
            float* cc = F.c[mt][nt];
            float e0 = ex2f(cc[0]), e1 = ex2f(cc[1]);
            float e2 = ex2f(cc[2]), e3 = ex2f(cc[3]);
            rlo += e0 + e1;
            rhi += e2 + e3;
            stage_sts(As, row,     col, pack_f16x2(e0, e1));
            stage_sts(As, row + 8, col, pack_f16x2(e2, e3));
        }
        rlo += __shfl_xor_sync(0xffffffffu, rlo, 1);
        rlo += __shfl_xor_sync(0xffffffffu, rlo, 2);
        rhi += __shfl_xor_sync(0xffffffffu, rhi, 1);
        rhi += __shfl_xor_sync(0xffffffffu, rhi, 2);
        if ((lane & 3) == 0) {
            int gr = b * SS + i0 + wm + mt * 16 + lr;
            atomicAdd(&g_l[gr], rlo);
            atomicAdd(&g_l[gr + 8], rhi);
        }
    }
    __syncthreads();

    // coalesced fp16 store of the 128x128 tile
    uint4* Eg = reinterpret_cast<uint4*>(g_E);
    #pragma unroll
    for (int it = 0; it < 16; it++) {
        int idx = tid + 128 * it;
        int row = idx >> 4, chunk = idx & 15;
        Eg[((size_t)(b * SS + i0 + row)) * 256 + (j0 >> 3) + chunk] =
            reinterpret_cast<uint4*>(As)[tidx(row, chunk)];
    }
}

// ---------------------------------------------------------------------------
// wsum: w[b][j] += sum_i u_i * E[b][i][j], u_i = sigmoid(theta-mu*t)/l_i
// grid (32, 16), block 256. Each CTA: 64 i's x all 2048 j's (1 uint4/thread/row).
// ---------------------------------------------------------------------------
__global__ void __launch_bounds__(256) wsum_kernel(const float* __restrict__ t,
                                                   const float* __restrict__ theta,
                                                   const float* __restrict__ mu) {
    __shared__ float us[64];
    const int b = blockIdx.y, ib = blockIdx.x * 64;
    const int tid = threadIdx.x;

    if (tid < 64) {
        int i = ib + tid;
        float z = theta[i] - mu[i] * t[b * SS + i];
        float tf = 1.f / (1.f + __expf(-z));
        us[tid] = tf / g_l[b * SS + i];
    }
    __syncthreads();

    const uint4* Eb = reinterpret_cast<const uint4*>(g_E) + (size_t)(b * SS + ib) * 256 + tid;

    float acc[8];
    #pragma unroll
    for (int p = 0; p < 8; p++) acc[p] = 0.f;

    #pragma unroll 8
    for (int ii = 0; ii < 64; ii++) {
        uint4 ev = Eb[(size_t)ii * 256];
        float uu = us[ii];
        const __half2* h = reinterpret_cast<const __half2*>(&ev);
        #pragma unroll
        for (int p = 0; p < 4; p++) {
            float2 f = __half22float2(h[p]);
            acc[2 * p]     += f.x * uu;
            acc[2 * p + 1] += f.y * uu;
        }
    }
    int j0 = b * SS + tid * 8;
    #pragma unroll
    for (int p = 0; p < 8; p++) atomicAdd(&g_w[j0 + p], acc[p]);
}

// ---------------------------------------------------------------------------
// v: v[b][d] = sum_j w[b][j] * x[b][j][d].  grid (16, 16), block 128.
// ---------------------------------------------------------------------------
__global__ void v_kernel(const float* __restrict__ x, float* __restrict__ out) {
    const int b = blockIdx.y, js = blockIdx.x, d = threadIdx.x;
    const float* wb = g_w + b * SS;
    float acc = 0.f;
    int j0 = js * 128;
    #pragma unroll 4
    for (int j = j0; j < j0 + 128; j++)
        acc += wb[j] * x[((size_t)b * SS + j) * DD + d];
    atomicAdd(&out[b * DD + d], acc);
}

// ---------------------------------------------------------------------------
extern "C" void kernel_launch(void* const* d_in, const int* in_sizes, int n_in,
                              void* d_out, int out_size) {
    const float* x     = (const float*)d_in[0];
    const float* t     = (const float*)d_in[1];
    const float* Wq    = (const float*)d_in[2];
    const float* Wk    = (const float*)d_in[3];
    const float* theta = (const float*)d_in[4];
    const float* mu    = (const float*)d_in[5];
    float* out = (float*)d_out;

    static bool attr_done = false;
    if (!attr_done) {
        cudaFuncSetAttribute(proj_kernel, cudaFuncAttributeMaxDynamicSharedMemorySize, 65536);
        cudaFuncSetAttribute(s1e_kernel,  cudaFuncAttributeMaxDynamicSharedMemorySize, 65536);
        attr_done = true;
    }

    prep_kernel<<<128, 256>>>(Wq, Wk, out);
    proj_kernel<<<dim3((BB * SS) / 128, 2), 128, 65536>>>(x);
    s1e_kernel<<<dim3(SS / 128, SS / 128, BB), 128, 65536>>>();
    wsum_kernel<<<dim3(SS / 64, BB), 256>>>(t, theta, mu);
    v_kernel<<<dim3(16, BB), 128>>>(x, out);
}

// round 12
// speedup vs baseline: 1.1443x; 1.1443x over previous
#include <cuda_runtime.h>
#include <cuda_fp16.h>
#include <cstdint>

#define BB 16
#define SS 2048
#define DD 128
#define UU 128

// ---------------------------------------------------------------------------
// Scratch (static __device__ — allocation-guard safe)
// ---------------------------------------------------------------------------
__device__ __half g_qh[(size_t)BB * SS * UU];   // q' = (x Wq)*log2e/sqrt(U), fp16 [row][u]
__device__ __half g_kh[(size_t)BB * SS * UU];   // k  =  x Wk, fp16 [row][u]
__device__ __half g_WT[256 * DD];               // [Wq*c | Wk] transposed: [n][d]
__device__ float g_l[BB * SS];
__device__ float g_w[BB * SS];

// ---------------------------------------------------------------------------
// helpers
// ---------------------------------------------------------------------------
__device__ __forceinline__ uint32_t smem_u32(const void* p) {
    uint32_t a;
    asm("{ .reg .u64 t; cvta.to.shared.u64 t, %1; cvt.u32.u64 %0, t; }" : "=r"(a) : "l"(p));
    return a;
}
__device__ __forceinline__ float ex2f(float x) {
    float r; asm("ex2.approx.f32 %0, %1;" : "=f"(r) : "f"(x)); return r;
}
__device__ __forceinline__ void ldmx4(uint32_t* r, uint32_t addr) {
    asm volatile("ldmatrix.sync.aligned.m8n8.x4.shared.b16 {%0,%1,%2,%3}, [%4];"
                 : "=r"(r[0]), "=r"(r[1]), "=r"(r[2]), "=r"(r[3]) : "r"(addr));
}
// fp32-accum MMA (used by proj for full precision)
__device__ __forceinline__ void mma16816(float* c, const uint32_t* a, uint32_t b0, uint32_t b1) {
    asm volatile(
        "mma.sync.aligned.m16n8k16.row.col.f32.f16.f16.f32 "
        "{%0,%1,%2,%3}, {%4,%5,%6,%7}, {%8,%9}, {%0,%1,%2,%3};"
        : "+f"(c[0]), "+f"(c[1]), "+f"(c[2]), "+f"(c[3])
        : "r"(a[0]), "r"(a[1]), "r"(a[2]), "r"(a[3]), "r"(b0), "r"(b1));
}
// fp16-accum MMA (2x rate, half the accumulator registers) — used by s1/s2
__device__ __forceinline__ void mma16816h(uint32_t* c, const uint32_t* a, uint32_t b0, uint32_t b1) {
    asm volatile(
        "mma.sync.aligned.m16n8k16.row.col.f16.f16.f16.f16 "
        "{%0,%1}, {%2,%3,%4,%5}, {%6,%7}, {%0,%1};"
        : "+r"(c[0]), "+r"(c[1])
        : "r"(a[0]), "r"(a[1]), "r"(a[2]), "r"(a[3]), "r"(b0), "r"(b1));
}
__device__ __forceinline__ uint32_t pack_f16x2(float lo, float hi) {
    uint32_t r;
    asm("cvt.rn.f16x2.f32 %0, %1, %2;" : "=r"(r) : "f"(hi), "f"(lo));
    return r;
}

// Swizzled smem tile: rows x 16 uint4 chunks (256B/row), chunk ^= (row&7).
__device__ __forceinline__ int tidx(int row, int chunk) {
    return row * 16 + (chunk ^ (row & 7));
}
__device__ __forceinline__ uint32_t taddr(uint32_t base, int row, int chunk) {
    return base + (uint32_t)tidx(row, chunk) * 16u;
}

// ---------------------------------------------------------------------------
// prep: zero g_l/g_w/out; g_WT[n][d] = (n<128 ? Wq[d][n]*C : Wk[d][n-128]) fp16
// ---------------------------------------------------------------------------
__global__ void prep_kernel(const float* __restrict__ Wq, const float* __restrict__ Wk,
                            float* __restrict__ out) {
    const float C_FOLD = 0.12751744695704165f;  // log2(e)/sqrt(128)
    int idx = blockIdx.x * 256 + threadIdx.x;   // 0..32767
    g_l[idx] = 0.f;
    g_w[idx] = 0.f;
    if (idx < BB * DD) out[idx] = 0.f;
    int n = idx >> 7, d = idx & 127;
    float v = (n < 128) ? Wq[d * 128 + n] * C_FOLD : Wk[d * 128 + (n - 128)];
    g_WT[idx] = __float2half(v);
}

// ---------------------------------------------------------------------------
// fp32-acc GEMM core (proj): 128x128, 4 warps, 64x64 warp tile.
// ---------------------------------------------------------------------------
struct Frag32 { float c[4][8][4]; };

__device__ __forceinline__ void gemm_core32(uint32_t aBase, uint32_t bBase, Frag32& F) {
    const int lane = threadIdx.x & 31, wid = threadIdx.x >> 5;
    const int wm = (wid & 1) * 64, wn = (wid >> 1) * 64;

    #pragma unroll
    for (int mt = 0; mt < 4; mt++)
        #pragma unroll
        for (int nt = 0; nt < 8; nt++)
            #pragma unroll
            for (int e = 0; e < 4; e++) F.c[mt][nt][e] = 0.f;

    const int l7 = lane & 7, lhi = lane >> 3;

    #pragma unroll
    for (int ks = 0; ks < 8; ks++) {
        uint32_t a[4][4];
        #pragma unroll
        for (int mt = 0; mt < 4; mt++) {
            int row = wm + mt * 16 + l7 + (lhi & 1) * 8;
            int chunk = 2 * ks + (lhi >> 1);
            ldmx4(a[mt], taddr(aBase, row, chunk));
        }
        uint32_t bfr[4][4];
        #pragma unroll
        for (int np = 0; np < 4; np++) {
            int row = wn + np * 16 + l7 + (lhi >> 1) * 8;
            int chunk = 2 * ks + (lhi & 1);
            ldmx4(bfr[np], taddr(bBase, row, chunk));
        }
        #pragma unroll
        for (int mt = 0; mt < 4; mt++)
            #pragma unroll
            for (int np = 0; np < 4; np++) {
                mma16816(F.c[mt][2 * np + 0], a[mt], bfr[np][0], bfr[np][1]);
                mma16816(F.c[mt][2 * np + 1], a[mt], bfr[np][2], bfr[np][3]);
            }
    }
}

// ---------------------------------------------------------------------------
// fp16-acc GEMM core (s1/s2): same tiling, 2x MMA rate, 64 acc regs/thread.
// c[mt][nt][0] = {row, col}, {row, col+1}; c[mt][nt][1] = {row+8, col}, {row+8, col+1}
// ---------------------------------------------------------------------------
struct Frag16 { uint32_t c[4][8][2]; };

__device__ __forceinline__ void gemm_core16(uint32_t aBase, uint32_t bBase, Frag16& F) {
    const int lane = threadIdx.x & 31, wid = threadIdx.x >> 5;
    const int wm = (wid & 1) * 64, wn = (wid >> 1) * 64;

    #pragma unroll
    for (int mt = 0; mt < 4; mt++)
        #pragma unroll
        for (int nt = 0; nt < 8; nt++) {
            F.c[mt][nt][0] = 0u;
            F.c[mt][nt][1] = 0u;
        }

    const int l7 = lane & 7, lhi = lane >> 3;

    #pragma unroll
    for (int ks = 0; ks < 8; ks++) {
        uint32_t a[4][4];
        #pragma unroll
        for (int mt = 0; mt < 4; mt++) {
            int row = wm + mt * 16 + l7 + (lhi & 1) * 8;
            int chunk = 2 * ks + (lhi >> 1);
            ldmx4(a[mt], taddr(aBase, row, chunk));
        }
        uint32_t bfr[4][4];
        #pragma unroll
        for (int np = 0; np < 4; np++) {
            int row = wn + np * 16 + l7 + (lhi >> 1) * 8;
            int chunk = 2 * ks + (lhi & 1);
            ldmx4(bfr[np], taddr(bBase, row, chunk));
        }
        #pragma unroll
        for (int mt = 0; mt < 4; mt++)
            #pragma unroll
            for (int np = 0; np < 4; np++) {
                mma16816h(F.c[mt][2 * np + 0], a[mt], bfr[np][0], bfr[np][1]);
                mma16816h(F.c[mt][2 * np + 1], a[mt], bfr[np][2], bfr[np][3]);
            }
    }
}

__device__ __forceinline__ void stage_sts(char* sm, int row, int col, uint32_t v) {
    uint32_t byte = (uint32_t)tidx(row, col >> 3) * 16u + (uint32_t)(col & 7) * 2u;
    *reinterpret_cast<uint32_t*>(sm + byte) = v;
}

// ---------------------------------------------------------------------------
// proj: rows r0..r0+127 of x (fp32->fp16) @ g_WT half -> q' or k (fp16)
// grid (256, 2), block 128, smem 64KB. fp32 accum (precision-critical).
// ---------------------------------------------------------------------------
__global__ void __launch_bounds__(128) proj_kernel(const float* __restrict__ x) {
    extern __shared__ char sm[];
    char* As = sm;
    char* Bs = sm + 32768;
    uint32_t aBase = smem_u32(As), bBase = smem_u32(Bs);

    const int tid = threadIdx.x;
    const int r0 = blockIdx.x * 128;
    const int nsel = blockIdx.y;

    {
        const float4* xs = reinterpret_cast<const float4*>(x + (size_t)r0 * DD);
        #pragma unroll
        for (int it = 0; it < 16; it++) {
            int idx = tid + 128 * it;
            int row = idx >> 4, chunk = idx & 15;
            float4 f0 = xs[row * 32 + chunk * 2];
            float4 f1 = xs[row * 32 + chunk * 2 + 1];
            uint4 o;
            o.x = pack_f16x2(f0.x, f0.y);
            o.y = pack_f16x2(f0.z, f0.w);
            o.z = pack_f16x2(f1.x, f1.y);
            o.w = pack_f16x2(f1.z, f1.w);
            reinterpret_cast<uint4*>(As)[tidx(row, chunk)] = o;
        }
        const uint4* ws = reinterpret_cast<const uint4*>(g_WT) + nsel * 128 * 16;
        #pragma unroll
        for (int it = 0; it < 16; it++) {
            int idx = tid + 128 * it;
            int row = idx >> 4, chunk = idx & 15;
            reinterpret_cast<uint4*>(Bs)[tidx(row, chunk)] = ws[idx];
        }
    }
    __syncthreads();

    Frag32 F;
    gemm_core32(aBase, bBase, F);
    __syncthreads();

    const int lane = tid & 31, wid = tid >> 5;
    const int wm = (wid & 1) * 64, wn = (wid >> 1) * 64;
    const int lr = lane >> 2, lc = (lane & 3) * 2;
    #pragma unroll
    for (int mt = 0; mt < 4; mt++)
        #pragma unroll
        for (int nt = 0; nt < 8; nt++) {
            int row = wm + mt * 16 + lr;
            int col = wn + nt * 8 + lc;
            float* cc = F.c[mt][nt];
            stage_sts(As, row,     col, pack_f16x2(cc[0], cc[1]));
            stage_sts(As, row + 8, col, pack_f16x2(cc[2], cc[3]));
        }
    __syncthreads();

    uint4* dst = reinterpret_cast<uint4*>(nsel ? g_kh : g_qh) + (size_t)r0 * 16;
    #pragma unroll
    for (int it = 0; it < 16; it++) {
        int idx = tid + 128 * it;
        int row = idx >> 4, chunk = idx & 15;
        dst[idx] = reinterpret_cast<uint4*>(As)[tidx(row, chunk)];
    }
}

// ---------------------------------------------------------------------------
// tile loader for S1/S2 (block = 128 threads)
// ---------------------------------------------------------------------------
__device__ __forceinline__ void load_qk_tiles(char* As, char* Bs, int b, int i0, int j0, int tid) {
    const uint4* qs = reinterpret_cast<const uint4*>(g_qh) + (size_t)(b * SS + i0) * 16;
    const uint4* ks = reinterpret_cast<const uint4*>(g_kh) + (size_t)(b * SS + j0) * 16;
    #pragma unroll
    for (int it = 0; it < 16; it++) {
        int idx = tid + 128 * it;
        int row = idx >> 4, chunk = idx & 15;
        reinterpret_cast<uint4*>(As)[tidx(row, chunk)] = qs[idx];
        reinterpret_cast<uint4*>(Bs)[tidx(row, chunk)] = ks[idx];
    }
}

// ---------------------------------------------------------------------------
// S1: l_i += sum_j exp2(q'_i . k_j)    grid (16,16,16), block 128
// ---------------------------------------------------------------------------
__global__ void __launch_bounds__(128) s1_kernel() {
    extern __shared__ char sm[];
    char* As = sm;
    char* Bs = sm + 32768;
    uint32_t aBase = smem_u32(As), bBase = smem_u32(Bs);

    const int tid = threadIdx.x;
    const int b = blockIdx.z, i0 = blockIdx.y * 128, j0 = blockIdx.x * 128;

    load_qk_tiles(As, Bs, b, i0, j0, tid);
    __syncthreads();

    Frag16 F;
    gemm_core16(aBase, bBase, F);

    const int lane = tid & 31, wid = tid >> 5;
    const int wm = (wid & 1) * 64;
    const int lr = lane >> 2;

    #pragma unroll
    for (int mt = 0; mt < 4; mt++) {
        float rlo = 0.f, rhi = 0.f;
        #pragma unroll
        for (int nt = 0; nt < 8; nt++) {
            float2 f01 = __half22float2(*reinterpret_cast<__half2*>(&F.c[mt][nt][0]));
            float2 f23 = __half22float2(*reinterpret_cast<__half2*>(&F.c[mt][nt][1]));
            rlo += ex2f(f01.x) + ex2f(f01.y);
            rhi += ex2f(f23.x) + ex2f(f23.y);
        }
        rlo += __shfl_xor_sync(0xffffffffu, rlo, 1);
        rlo += __shfl_xor_sync(0xffffffffu, rlo, 2);
        rhi += __shfl_xor_sync(0xffffffffu, rhi, 1);
        rhi += __shfl_xor_sync(0xffffffffu, rhi, 2);
        if ((lane & 3) == 0) {
            int gr = b * SS + i0 + wm + mt * 16 + lr;
            atomicAdd(&g_l[gr], rlo);
            atomicAdd(&g_l[gr + 8], rhi);
        }
    }
}

// ---------------------------------------------------------------------------
// S2: w_j += sum_i u_i * exp2(q'_i . k_j),  u_i = sigmoid(theta-mu*t)/l_i
// grid (16,16,16), block 128, smem 64KB + 512B
// ---------------------------------------------------------------------------
__global__ void __launch_bounds__(128) s2_kernel(const float* __restrict__ t,
                                                 const float* __restrict__ theta,
                                                 const float* __restrict__ mu) {
    extern __shared__ char sm[];
    char* As = sm;
    char* Bs = sm + 32768;
    float* us = reinterpret_cast<float*>(sm + 65536);
    uint32_t aBase = smem_u32(As), bBase = smem_u32(Bs);

    const int tid = threadIdx.x;
    const int b = blockIdx.z, i0 = blockIdx.y * 128, j0 = blockIdx.x * 128;

    load_qk_tiles(As, Bs, b, i0, j0, tid);
    {
        int i = i0 + tid;
        float z = theta[i] - mu[i] * t[b * SS + i];
        float tf = 1.f / (1.f + __expf(-z));
        us[tid] = tf / g_l[b * SS + i];
    }
    __syncthreads();

    Frag16 F;
    gemm_core16(aBase, bBase, F);

    const int lane = tid & 31, wid = tid >> 5;
    const int wm = (wid & 1) * 64, wn = (wid >> 1) * 64;
    const int lr = lane >> 2;

    float s[8][2];
    #pragma unroll
    for (int nt = 0; nt < 8; nt++) { s[nt][0] = 0.f; s[nt][1] = 0.f; }

    #pragma unroll
    for (int mt = 0; mt < 4; mt++) {
        float ulo = us[wm + mt * 16 + lr];
        float uhi = us[wm + mt * 16 + lr + 8];
        #pragma unroll
        for (int nt = 0; nt < 8; nt++) {
            float2 f01 = __half22float2(*reinterpret_cast<__half2*>(&F.c[mt][nt][0]));
            float2 f23 = __half22float2(*reinterpret_cast<__half2*>(&F.c[mt][nt][1]));
            s[nt][0] += ulo * ex2f(f01.x) + uhi * ex2f(f23.x);
            s[nt][1] += ulo * ex2f(f01.y) + uhi * ex2f(f23.y);
        }
    }

    // reduce over rows: lanes with equal (lane&3) — xor masks 4, 8, 16
    #pragma unroll
    for (int nt = 0; nt < 8; nt++)
        #pragma unroll
        for (int p = 0; p < 2; p++) {
            float v = s[nt][p];
            v += __shfl_xor_sync(0xffffffffu, v, 4);
            v += __shfl_xor_sync(0xffffffffu, v, 8);
            v += __shfl_xor_sync(0xffffffffu, v, 16);
            s[nt][p] = v;
        }
    if (lane < 4) {
        #pragma unroll
        for (int nt = 0; nt < 8; nt++) {
            int col = j0 + wn + nt * 8 + lane * 2;
            atomicAdd(&g_w[b * SS + col],     s[nt][0]);
            atomicAdd(&g_w[b * SS + col + 1], s[nt][1]);
        }
    }
}

// ---------------------------------------------------------------------------
// v: v[b][d] = sum_j w[b][j] * x[b][j][d].  grid (16, 16), block 128.
// ---------------------------------------------------------------------------
__global__ void v_kernel(const float* __restrict__ x, float* __restrict__ out) {
    const int b = blockIdx.y, js = blockIdx.x, d = threadIdx.x;
    const float* wb = g_w + b * SS;
    float acc = 0.f;
    int j0 = js * 128;
    #pragma unroll 4
    for (int j = j0; j < j0 + 128; j++)
        acc += wb[j] * x[((size_t)b * SS + j) * DD + d];
    atomicAdd(&out[b * DD + d], acc);
}

// ---------------------------------------------------------------------------
extern "C" void kernel_launch(void* const* d_in, const int* in_sizes, int n_in,
                              void* d_out, int out_size) {
    const float* x     = (const float*)d_in[0];
    const float* t     = (const float*)d_in[1];
    const float* Wq    = (const float*)d_in[2];
    const float* Wk    = (const float*)d_in[3];
    const float* theta = (const float*)d_in[4];
    const float* mu    = (const float*)d_in[5];
    float* out = (float*)d_out;

    static bool attr_done = false;
    if (!attr_done) {
        cudaFuncSetAttribute(proj_kernel, cudaFuncAttributeMaxDynamicSharedMemorySize, 65536);
        cudaFuncSetAttribute(s1_kernel,   cudaFuncAttributeMaxDynamicSharedMemorySize, 65536);
        cudaFuncSetAttribute(s2_kernel,   cudaFuncAttributeMaxDynamicSharedMemorySize, 66560);
        attr_done = true;
    }

    prep_kernel<<<128, 256>>>(Wq, Wk, out);
    proj_kernel<<<dim3((BB * SS) / 128, 2), 128, 65536>>>(x);
    s1_kernel<<<dim3(SS / 128, SS / 128, BB), 128, 65536>>>();
    s2_kernel<<<dim3(SS / 128, SS / 128, BB), 128, 66560>>>(t, theta, mu);
    v_kernel<<<dim3(16, BB), 128>>>(x, out);
}